// round 14
// baseline (speedup 1.0000x reference)
#include <cuda_runtime.h>
#include <cstdint>

// Problem dims
#define NB 16
#define NS_SEQ 2048
#define ND 512
#define NH 256
#define NROWS 32768   // NB*NS_SEQ
#define NHID 1024

// ---------------- scratch (static device memory; no allocations) ----------------
__device__ float g_xn[(long)NROWS * ND];
__device__ float g_zx[(long)NROWS * 2048];
__device__ float g_h1[(long)NROWS * ND];
__device__ float g_h2[(long)NROWS * ND];
__device__ float g_gpre[(long)NROWS * NHID];
__device__ unsigned char g_apply[NROWS];

// ---------------- helpers ----------------
__device__ __forceinline__ float ftanh_(float x) {
    float r; asm("tanh.approx.f32 %0, %1;" : "=f"(r) : "f"(x)); return r;
}
__device__ __forceinline__ float fsig(float x) {
    return 0.5f * ftanh_(0.5f * x) + 0.5f;
}

// ---------------- LayerNorm ----------------
template <int COLS, bool RELU>
__global__ __launch_bounds__(128) void ln_kernel(const float* __restrict__ in,
                                                 float* __restrict__ out,
                                                 const float* __restrict__ gamma,
                                                 const float* __restrict__ beta) {
    constexpr int V = COLS / 512;
    long row = blockIdx.x;
    const float4* ip = (const float4*)(in + row * (long)COLS);
    int tid = threadIdx.x;
    float4 v[V];
    float s = 0.f, ss = 0.f;
#pragma unroll
    for (int i = 0; i < V; i++) {
        v[i] = ip[i * 128 + tid];
        s += v[i].x + v[i].y + v[i].z + v[i].w;
        ss += v[i].x * v[i].x + v[i].y * v[i].y + v[i].z * v[i].z + v[i].w * v[i].w;
    }
#pragma unroll
    for (int o = 16; o > 0; o >>= 1) {
        s += __shfl_xor_sync(0xffffffffu, s, o);
        ss += __shfl_xor_sync(0xffffffffu, ss, o);
    }
    __shared__ float red[8];
    int wid = tid >> 5;
    if ((tid & 31) == 0) { red[wid] = s; red[4 + wid] = ss; }
    __syncthreads();
    s = red[0] + red[1] + red[2] + red[3];
    ss = red[4] + red[5] + red[6] + red[7];
    float mean = s * (1.0f / COLS);
    float var = ss * (1.0f / COLS) - mean * mean;
    float rstd = rsqrtf(var + 1e-5f);
    float4* op = (float4*)(out + row * (long)COLS);
#pragma unroll
    for (int i = 0; i < V; i++) {
        int c0 = (i * 128 + tid) * 4;
        float4 g4 = *(const float4*)(gamma + c0);
        float4 b4 = *(const float4*)(beta + c0);
        float4 r;
        r.x = (v[i].x - mean) * rstd * g4.x + b4.x;
        r.y = (v[i].y - mean) * rstd * g4.y + b4.y;
        r.z = (v[i].z - mean) * rstd * g4.z + b4.z;
        r.w = (v[i].w - mean) * rstd * g4.w + b4.w;
        if (RELU) {
            r.x = fmaxf(r.x, 0.f); r.y = fmaxf(r.y, 0.f);
            r.z = fmaxf(r.z, 0.f); r.w = fmaxf(r.w, 0.f);
        }
        op[i * 128 + tid] = r;
    }
}

// ---------------- decide scan ----------------
__global__ void decide_kernel(const float* __restrict__ rnd,
                              const void* __restrict__ maskv,
                              unsigned char* __restrict__ apply) {
    int b = threadIdx.x;
    if (b >= NB) return;
    unsigned int w0 = ((const unsigned int*)maskv)[0];
    int enc = (w0 == 0x01010101u) ? 0 : (w0 == 0x3F800000u) ? 2 : (w0 == 1u) ? 1 : 0;
    const unsigned char* m8 = (const unsigned char*)maskv;
    const int* m32 = (const int*)maskv;
    const float* mf = (const float*)maskv;
    long base = (long)b * NS_SEQ;
    int last = -1000000000;
    int cons = 0;
    for (int pos = 0; pos < NS_SEQ; pos++) {
        float r = rnd[base + pos];
        long i = base + pos;
        bool m = (enc == 0) ? (m8[i] != 0) : (enc == 1) ? (m32[i] != 0) : (mf[i] != 0.0f);
        bool iok = (pos == 0) || (pos - last >= 2);
        bool ap = m && (r < 0.5f) && iok && (cons < 2);
        last = ap ? pos : last;
        cons = ap ? cons + 1 : (m ? 0 : cons);
        apply[i] = ap ? (unsigned char)1 : (unsigned char)0;
    }
}

// ================= tf32 mma.sync GEMM with ldmatrix fragments (R9, passing) =================
#define SROW 36

__device__ __forceinline__ uint32_t cvt_tf32(float x) {
    uint32_t r; asm("cvt.rn.tf32.f32 %0, %1;" : "=r"(r) : "f"(x)); return r;
}
__device__ __forceinline__ void mma8(float* c, const uint32_t* a, const uint32_t* b) {
    asm volatile("mma.sync.aligned.m16n8k8.row.col.f32.tf32.tf32.f32 "
                 "{%0,%1,%2,%3}, {%4,%5,%6,%7}, {%8,%9}, {%0,%1,%2,%3};"
                 : "+f"(c[0]), "+f"(c[1]), "+f"(c[2]), "+f"(c[3])
                 : "r"(a[0]), "r"(a[1]), "r"(a[2]), "r"(a[3]), "r"(b[0]), "r"(b[1]));
}
__device__ __forceinline__ void ldsm4(uint32_t* r, uint32_t addr) {
    asm volatile("ldmatrix.sync.aligned.m8n8.x4.shared.b16 {%0,%1,%2,%3}, [%4];"
                 : "=r"(r[0]), "=r"(r[1]), "=r"(r[2]), "=r"(r[3]) : "r"(addr));
}

template <int MODE>
__global__ __launch_bounds__(256) void tf32_gemm_kernel(
    const float* __restrict__ A1, const float* __restrict__ A2, int Ksplit, int K,
    const float* __restrict__ W, const float* __restrict__ bias,
    float* __restrict__ C, int N,
    const unsigned char* __restrict__ apply, const float* __restrict__ xn) {
    __shared__ uint32_t As[128 * SROW];
    __shared__ uint32_t Bs[128 * SROW];

    const int tid = threadIdx.x;
    const int wid = tid >> 5;
    const int lane = tid & 31;
    const int m0 = blockIdx.y * 128, n0 = blockIdx.x * 128;
    const int lda2 = K - Ksplit;
    const int warp_m = wid & 1, warp_n = wid >> 1;
    const int g4 = lane >> 2;
    const int t4 = lane & 3;

    const int lrow = tid >> 1;
    const int lhalf = tid & 1;

    const uint32_t aBase = (uint32_t)__cvta_generic_to_shared(As);
    const uint32_t bBase = (uint32_t)__cvta_generic_to_shared(Bs);
    const uint32_t a_off = aBase + (uint32_t)(warp_m * 64 + (lane & 15)) * 144u
                         + (uint32_t)(lane >> 4) * 16u;
    const uint32_t b_off = bBase + (uint32_t)(warp_n * 32 + (lane & 7) + ((lane >> 4) << 3)) * 144u
                         + (uint32_t)((lane >> 3) & 1) * 16u;

    float acc[4][4][4];
#pragma unroll
    for (int i = 0; i < 4; i++)
#pragma unroll
        for (int j = 0; j < 4; j++)
#pragma unroll
            for (int u = 0; u < 4; u++) acc[i][j][u] = 0.f;

    const int NT = K >> 5;
    float4 av[4], bv[4];
    {
        const int gc = lhalf << 4;
        const float* asrc = (gc < Ksplit) ? (A1 + (long)(m0 + lrow) * Ksplit + gc)
                                          : (A2 + (long)(m0 + lrow) * lda2 + (gc - Ksplit));
        const float* bsrc = W + (long)(n0 + lrow) * K + gc;
#pragma unroll
        for (int q = 0; q < 4; q++) { av[q] = ((const float4*)asrc)[q]; bv[q] = ((const float4*)bsrc)[q]; }
    }
#pragma unroll
    for (int q = 0; q < 4; q++) {
        int cbase = lrow * SROW + lhalf * 16 + q * 4;
        *(uint4*)&As[cbase] = make_uint4(cvt_tf32(av[q].x), cvt_tf32(av[q].y), cvt_tf32(av[q].z), cvt_tf32(av[q].w));
        *(uint4*)&Bs[cbase] = make_uint4(cvt_tf32(bv[q].x), cvt_tf32(bv[q].y), cvt_tf32(bv[q].z), cvt_tf32(bv[q].w));
    }
    __syncthreads();

    for (int t = 0; t < NT; t++) {
        if (t + 1 < NT) {
            const int gc = ((t + 1) << 5) + (lhalf << 4);
            const float* asrc = (gc < Ksplit) ? (A1 + (long)(m0 + lrow) * Ksplit + gc)
                                              : (A2 + (long)(m0 + lrow) * lda2 + (gc - Ksplit));
            const float* bsrc = W + (long)(n0 + lrow) * K + gc;
#pragma unroll
            for (int q = 0; q < 4; q++) { av[q] = ((const float4*)asrc)[q]; bv[q] = ((const float4*)bsrc)[q]; }
        }
#pragma unroll
        for (int ks = 0; ks < 4; ks++) {
            uint32_t afr[4][4], bfr[4][2];
            const uint32_t kqb = (uint32_t)(ks * 32);
#pragma unroll
            for (int i = 0; i < 4; i++)
                ldsm4(afr[i], a_off + (uint32_t)(i * 16 * 144) + kqb);
#pragma unroll
            for (int p = 0; p < 2; p++) {
                uint32_t br[4];
                ldsm4(br, b_off + (uint32_t)(p * 16 * 144) + kqb);
                bfr[2 * p][0] = br[0]; bfr[2 * p][1] = br[1];
                bfr[2 * p + 1][0] = br[2]; bfr[2 * p + 1][1] = br[3];
            }
#pragma unroll
            for (int i = 0; i < 4; i++)
#pragma unroll
                for (int j = 0; j < 4; j++) mma8(acc[i][j], afr[i], bfr[j]);
        }
        __syncthreads();
        if (t + 1 < NT) {
#pragma unroll
            for (int q = 0; q < 4; q++) {
                int cbase = lrow * SROW + lhalf * 16 + q * 4;
                *(uint4*)&As[cbase] = make_uint4(cvt_tf32(av[q].x), cvt_tf32(av[q].y), cvt_tf32(av[q].z), cvt_tf32(av[q].w));
                *(uint4*)&Bs[cbase] = make_uint4(cvt_tf32(bv[q].x), cvt_tf32(bv[q].y), cvt_tf32(bv[q].z), cvt_tf32(bv[q].w));
            }
            __syncthreads();
        }
    }

#pragma unroll
    for (int i = 0; i < 4; i++) {
        long r0 = m0 + warp_m * 64 + i * 16 + g4;
        long r1 = r0 + 8;
        unsigned char ap0 = 0, ap1 = 0;
        if (MODE == 1) { ap0 = apply[r0]; ap1 = apply[r1]; }
#pragma unroll
        for (int j = 0; j < 4; j++) {
            int c = n0 + warp_n * 32 + j * 8 + 2 * t4;
            float v00 = acc[i][j][0] + bias[c];
            float v01 = acc[i][j][1] + bias[c + 1];
            float v10 = acc[i][j][2] + bias[c];
            float v11 = acc[i][j][3] + bias[c + 1];
            if (MODE == 0) {
                *(float2*)(C + r0 * (long)N + c) = make_float2(v00, v01);
                *(float2*)(C + r1 * (long)N + c) = make_float2(v10, v11);
            } else {
                float2 x0 = *(const float2*)(xn + r0 * 512 + c);
                float2 x1 = *(const float2*)(xn + r1 * 512 + c);
                float p00, p01, p10, p11;
                if (c < 256)      { p00 = fminf(fmaxf(v00, 0.f), 1.f); p10 = fminf(fmaxf(v10, 0.f), 1.f); }
                else if (c < 384) { p00 = v00 * 0.3f; p10 = v10 * 0.3f; }
                else if (c < 448) { p00 = v00 * 0.7f; p10 = v10 * 0.7f; }
                else              { p00 = v00 + 0.05f; p10 = v10 + 0.05f; }
                int c1 = c + 1;
                if (c1 < 256)      { p01 = fminf(fmaxf(v01, 0.f), 1.f); p11 = fminf(fmaxf(v11, 0.f), 1.f); }
                else if (c1 < 384) { p01 = v01 * 0.3f; p11 = v11 * 0.3f; }
                else if (c1 < 448) { p01 = v01 * 0.7f; p11 = v11 * 0.7f; }
                else               { p01 = v01 + 0.05f; p11 = v11 + 0.05f; }
                *(float2*)(C + r0 * 512 + c) = make_float2(ap0 ? p00 : x0.x, ap0 ? p01 : x0.y);
                *(float2*)(C + r1 * 512 + c) = make_float2(ap1 ? p10 : x1.x, ap1 ? p11 : x1.y);
            }
        }
    }
}

// ================= BiLSTM recurrence v8: gate-aligned fragment permutation =================
// Warp w's 16-row m-tile = [i:u0..3 | f:u0..3 | g:u0..3 | o:u0..3] for units
// u = 4w..4w+3. After MMA, lane 4*g4 (g4<4) holds i,g of unit 4w+g4; its xor-16
// partner holds f,o. One shfl.xor(16) -> gates computed inside the MMA warps:
// no zredv, no per-step __syncthreads, no 2-warp tail. Cluster barrier split
// into arrive (step end) / wait (next step top, after zx prefetch issue).
// hstage burst-flush every 8 steps kept from R13.

__device__ __forceinline__ void cluster_sync_() {
    asm volatile("barrier.cluster.arrive.aligned;" ::: "memory");
    asm volatile("barrier.cluster.wait.aligned;" ::: "memory");
}

__global__ __launch_bounds__(256, 1) __cluster_dims__(8, 1, 1)
void lstm_kernel(const float* __restrict__ zx, const float* __restrict__ whh,
                 float* __restrict__ hout) {
    __shared__ float hbuf[2][2][272];
    __shared__ float hstage[8][2][32];

    const int rank = blockIdx.x & 7;
    const int cl = blockIdx.x >> 3;
    const int dir = cl >> 3;
    const int bp = cl & 7;
    const int tid = threadIdx.x;
    const int wid = tid >> 5;
    const int lane = tid & 31;
    const int g4 = lane >> 2;    // fragment row 0..7
    const int t4 = lane & 3;

    // permuted row map: fragment row r -> Whh row dir*1024 + (r>>2)*256 + rank*32 + 4*wid + (r&3)
    const int uloc = 4 * wid + (g4 & 3);               // unit local 0..31 (for rows g4, g4+8)
    const long rowA = (long)dir * 1024 + (g4 >> 2) * 256 + rank * 32 + uloc;       // gates i/f
    const long rowB = rowA + 512;                                                   // gates g/o

    // Whh A-fragments, loaded once
    uint32_t wA[32][4];
    {
        const float* wpA = whh + rowA * 256;
        const float* wpB = whh + rowB * 256;
#pragma unroll
        for (int q = 0; q < 32; q++) {
            int k0 = q * 8 + t4;
            wA[q][0] = cvt_tf32(wpA[k0]);
            wA[q][1] = cvt_tf32(wpB[k0]);
            wA[q][2] = cvt_tf32(wpA[k0 + 4]);
            wA[q][3] = cvt_tf32(wpB[k0 + 4]);
        }
    }

    for (int i = tid; i < 2 * 2 * 272; i += 256) (&hbuf[0][0][0])[i] = 0.f;
    __syncthreads();
    cluster_sync_();

    const long nb0 = (long)(bp * 2) * NS_SEQ;
    const long nb1 = (long)(bp * 2 + 1) * NS_SEQ;
    const int bb = g4 & 1;       // B-operand batch column for this lane

    // gate-holder lanes: t4==0 && g4<4 ; unit = 4*wid + g4
    const bool gater = (t4 == 0) && (g4 < 4);
    const int guG = rank * 32 + 4 * wid + (g4 & 3);     // global unit (0..255) for gaters
    uint32_t rA[8];
    {
        const int off = ((guG >> 6) * 68) + (guG & 63);
        uint32_t laddr = (uint32_t)__cvta_generic_to_shared(&hbuf[0][0][off]);
#pragma unroll
        for (int p = 0; p < 8; p++)
            asm("mapa.shared::cluster.u32 %0, %1, %2;" : "=r"(rA[p]) : "r"(laddr), "r"(p));
    }

    float cst0 = 0.f, cst1 = 0.f;

    float zx00 = 0, zx01 = 0, zx10 = 0, zx11 = 0;
    if (t4 == 0) {
        int s0 = dir ? (NS_SEQ - 1) : 0;
        zx00 = zx[(nb0 + s0) * 2048 + rowA];
        zx01 = zx[(nb1 + s0) * 2048 + rowA];
        zx10 = zx[(nb0 + s0) * 2048 + rowB];
        zx11 = zx[(nb1 + s0) * 2048 + rowB];
    }

    int buf = 0;
    for (int t = 0; t < NS_SEQ; t++) {
        // prefetch next step's zx (issued before the wait -> overlaps barrier)
        float nx00 = 0, nx01 = 0, nx10 = 0, nx11 = 0;
        if (t4 == 0 && t < NS_SEQ - 1) {
            int sn = dir ? (NS_SEQ - 2 - t) : (t + 1);
            nx00 = zx[(nb0 + sn) * 2048 + rowA];
            nx01 = zx[(nb1 + sn) * 2048 + rowA];
            nx10 = zx[(nb0 + sn) * 2048 + rowB];
            nx11 = zx[(nb1 + sn) * 2048 + rowB];
        }
        if (t > 0)
            asm volatile("barrier.cluster.wait.aligned;" ::: "memory");

        // z = Whh_perm @ h : 32 x mma.m16n8k8.tf32, 4 independent accumulators
        float ca[4] = {0, 0, 0, 0}, cb[4] = {0, 0, 0, 0};
        float cc[4] = {0, 0, 0, 0}, cd[4] = {0, 0, 0, 0};
        const float* hb = &hbuf[buf][bb][0];
#pragma unroll
        for (int q = 0; q < 32; q += 4) {
            uint32_t b0[2], b1[2], b2[2], b3[2];
            {
                int k = q * 8 + t4;
                b0[0] = __float_as_uint(hb[((k >> 6) * 68) + (k & 63)]);
                int k2 = k + 4;
                b0[1] = __float_as_uint(hb[((k2 >> 6) * 68) + (k2 & 63)]);
                k = (q + 1) * 8 + t4;
                b1[0] = __float_as_uint(hb[((k >> 6) * 68) + (k & 63)]);
                k2 = k + 4;
                b1[1] = __float_as_uint(hb[((k2 >> 6) * 68) + (k2 & 63)]);
                k = (q + 2) * 8 + t4;
                b2[0] = __float_as_uint(hb[((k >> 6) * 68) + (k & 63)]);
                k2 = k + 4;
                b2[1] = __float_as_uint(hb[((k2 >> 6) * 68) + (k2 & 63)]);
                k = (q + 3) * 8 + t4;
                b3[0] = __float_as_uint(hb[((k >> 6) * 68) + (k & 63)]);
                k2 = k + 4;
                b3[1] = __float_as_uint(hb[((k2 >> 6) * 68) + (k2 & 63)]);
            }
            mma8(ca, wA[q], b0);
            mma8(cb, wA[q + 1], b1);
            mma8(cc, wA[q + 2], b2);
            mma8(cd, wA[q + 3], b3);
        }
        // s0..s3: rows (g4 | g4+8) x batch (0 | 1), + zx on col-holder lanes
        float s0 = ca[0] + cb[0] + cc[0] + cd[0];
        float s1 = ca[1] + cb[1] + cc[1] + cd[1];
        float s2 = ca[2] + cb[2] + cc[2] + cd[2];
        float s3 = ca[3] + cb[3] + cc[3] + cd[3];
        if (t4 == 0) { s0 += zx00; s1 += zx01; s2 += zx10; s3 += zx11; }

        // partner exchange: lane 4*g4 <-> lane 4*(g4^4) (i,g <-> f,o)
        float f0 = __shfl_xor_sync(0xffffffffu, s0, 16);
        float f1 = __shfl_xor_sync(0xffffffffu, s1, 16);
        float f2 = __shfl_xor_sync(0xffffffffu, s2, 16);
        float f3 = __shfl_xor_sync(0xffffffffu, s3, 16);

        if (gater) {
            // own: zi (s0,s1), zg (s2,s3) ; partner: zf (f0,f1), zo (f2,f3)
            float ig0 = fsig(s0), fg0 = fsig(f0), gg0 = ftanh_(s2), og0 = fsig(f2);
            cst0 = fg0 * cst0 + ig0 * gg0;
            float h0 = og0 * ftanh_(cst0);
            float ig1 = fsig(s1), fg1 = fsig(f1), gg1 = ftanh_(s3), og1 = fsig(f3);
            cst1 = fg1 * cst1 + ig1 * gg1;
            float h1 = og1 * ftanh_(cst1);
            float hr0 = __uint_as_float(cvt_tf32(h0));
            float hr1 = __uint_as_float(cvt_tf32(h1));
            const uint32_t bo = (uint32_t)(buf ^ 1) * 2176u;   // hbuf slot stride bytes
#pragma unroll
            for (int p = 0; p < 8; p++) {
                asm volatile("st.shared::cluster.f32 [%0], %1;" :: "r"(rA[p] + bo), "f"(hr0) : "memory");
                asm volatile("st.shared::cluster.f32 [%0], %1;" :: "r"(rA[p] + bo + 1088u), "f"(hr1) : "memory");
            }
            hstage[t & 7][0][guG & 31] = hr0;
            hstage[t & 7][1][guG & 31] = hr1;
        }

        // burst-flush staged h every 8 steps (coalesced; drain amortized)
        if ((t & 7) == 7) {
            __syncthreads();
            const int obase = dir * 256 + rank * 32;
            for (int idx = tid; idx < 512; idx += 256) {
                int j = idx >> 6;
                int r = idx & 63;
                int b = r >> 5, u = r & 31;
                int tb = t - 7 + j;
                int sj = dir ? (NS_SEQ - 1 - tb) : tb;
                const long nb = b ? nb1 : nb0;
                hout[(nb + sj) * 512 + obase + u] = hstage[j][b][u];
            }
            __syncthreads();
        }
        asm volatile("barrier.cluster.arrive.aligned;" ::: "memory");
        buf ^= 1;
        zx00 = nx00; zx01 = nx01; zx10 = nx10; zx11 = nx11;
    }
    // match the final arrive; also protects SMEM from peer stores at exit
    asm volatile("barrier.cluster.wait.aligned;" ::: "memory");
}

// ---------------- launch ----------------
extern "C" void kernel_launch(void* const* d_in, const int* in_sizes, int n_in,
                              void* d_out, int out_size) {
    const float* features = (const float*)d_in[0];
    const void* mask = d_in[1];
    const float* rnd = (const float*)d_in[2];
    const float* ln_g = (const float*)d_in[3];
    const float* ln_b = (const float*)d_in[4];
    const float* Wih0 = (const float*)d_in[5];
    const float* Whh0 = (const float*)d_in[6];
    const float* b0 = (const float*)d_in[7];
    const float* Wih1 = (const float*)d_in[8];
    const float* Whh1 = (const float*)d_in[9];
    const float* b1 = (const float*)d_in[10];
    const float* gW1 = (const float*)d_in[11];
    const float* gb1 = (const float*)d_in[12];
    const float* gln_g = (const float*)d_in[13];
    const float* gln_b = (const float*)d_in[14];
    const float* gW2 = (const float*)d_in[15];
    const float* gb2 = (const float*)d_in[16];
    float* out = (float*)d_out;

    float *xn, *zx, *h1, *h2, *gpre;
    unsigned char* apl;
    cudaGetSymbolAddress((void**)&xn, g_xn);
    cudaGetSymbolAddress((void**)&zx, g_zx);
    cudaGetSymbolAddress((void**)&h1, g_h1);
    cudaGetSymbolAddress((void**)&h2, g_h2);
    cudaGetSymbolAddress((void**)&gpre, g_gpre);
    cudaGetSymbolAddress((void**)&apl, g_apply);

    // 1. LayerNorm(features) -> xn
    ln_kernel<512, false><<<NROWS, 128>>>(features, xn, ln_g, ln_b);
    // 2. decide scan -> apply
    decide_kernel<<<1, 32>>>(rnd, mask, apl);
    // 3. layer0 input projections: zx = xn @ Wih0cat^T + b0   [32768 x 2048]
    tf32_gemm_kernel<0><<<dim3(16, 256), 256>>>(xn, xn, 512, 512, Wih0, b0, zx, 2048, nullptr, nullptr);
    // 4. layer0 recurrence -> h1
    lstm_kernel<<<128, 256>>>(zx, Whh0, h1);
    // 5. layer1 input projections: zx = h1 @ Wih1cat^T + b1
    tf32_gemm_kernel<0><<<dim3(16, 256), 256>>>(h1, h1, 512, 512, Wih1, b1, zx, 2048, nullptr, nullptr);
    // 6. layer1 recurrence -> h2
    lstm_kernel<<<128, 256>>>(zx, Whh1, h2);
    // 7. gpre = [xn | h2] @ gW1^T + gb1   [32768 x 1024]
    tf32_gemm_kernel<0><<<dim3(8, 256), 256>>>(xn, h2, 512, 1024, gW1, gb1, gpre, 1024, nullptr, nullptr);
    // 8. LN + ReLU in place
    ln_kernel<1024, true><<<NROWS, 128>>>(gpre, gpre, gln_g, gln_b);
    // 9. orn (first 512 cols of gW2) + ornament transform + apply-select -> out
    tf32_gemm_kernel<1><<<dim3(4, 256), 256>>>(gpre, gpre, 1024, 1024, gW2, gb2, out, 512, apl, xn);
}

// round 15
// speedup vs baseline: 1.1127x; 1.1127x over previous
#include <cuda_runtime.h>
#include <cstdint>

// Problem dims
#define NB 16
#define NS_SEQ 2048
#define ND 512
#define NH 256
#define NROWS 32768   // NB*NS_SEQ
#define NHID 1024

// ---------------- scratch (static device memory; no allocations) ----------------
__device__ float g_xn[(long)NROWS * ND];
__device__ float g_zx[(long)NROWS * 2048];
__device__ float g_h1[(long)NROWS * ND];
__device__ float g_h2[(long)NROWS * ND];
__device__ float g_gpre[(long)NROWS * NHID];
__device__ unsigned char g_apply[NROWS];
__device__ float g_wtf[5242880];   // tf32-rounded weights: Wih0|Wih1|gW1|gW2

// ---------------- helpers ----------------
__device__ __forceinline__ float ftanh_(float x) {
    float r; asm("tanh.approx.f32 %0, %1;" : "=f"(r) : "f"(x)); return r;
}
__device__ __forceinline__ float fsig(float x) {
    return 0.5f * ftanh_(0.5f * x) + 0.5f;
}
__device__ __forceinline__ uint32_t cvt_tf32(float x) {
    uint32_t r; asm("cvt.rn.tf32.f32 %0, %1;" : "=r"(r) : "f"(x)); return r;
}

// ---------------- weight tf32 pre-round ----------------
__global__ void cvtw_kernel(const float* __restrict__ src, float* __restrict__ dst, int n) {
    int i = blockIdx.x * 256 + threadIdx.x;
    if (i < n) dst[i] = __uint_as_float(cvt_tf32(src[i]));
}

// ---------------- LayerNorm (outputs tf32-rounded: they feed GEMM A operands) ----------------
template <int COLS, bool RELU>
__global__ __launch_bounds__(128) void ln_kernel(const float* __restrict__ in,
                                                 float* __restrict__ out,
                                                 const float* __restrict__ gamma,
                                                 const float* __restrict__ beta) {
    constexpr int V = COLS / 512;
    long row = blockIdx.x;
    const float4* ip = (const float4*)(in + row * (long)COLS);
    int tid = threadIdx.x;
    float4 v[V];
    float s = 0.f, ss = 0.f;
#pragma unroll
    for (int i = 0; i < V; i++) {
        v[i] = ip[i * 128 + tid];
        s += v[i].x + v[i].y + v[i].z + v[i].w;
        ss += v[i].x * v[i].x + v[i].y * v[i].y + v[i].z * v[i].z + v[i].w * v[i].w;
    }
#pragma unroll
    for (int o = 16; o > 0; o >>= 1) {
        s += __shfl_xor_sync(0xffffffffu, s, o);
        ss += __shfl_xor_sync(0xffffffffu, ss, o);
    }
    __shared__ float red[8];
    int wid = tid >> 5;
    if ((tid & 31) == 0) { red[wid] = s; red[4 + wid] = ss; }
    __syncthreads();
    s = red[0] + red[1] + red[2] + red[3];
    ss = red[4] + red[5] + red[6] + red[7];
    float mean = s * (1.0f / COLS);
    float var = ss * (1.0f / COLS) - mean * mean;
    float rstd = rsqrtf(var + 1e-5f);
    float4* op = (float4*)(out + row * (long)COLS);
#pragma unroll
    for (int i = 0; i < V; i++) {
        int c0 = (i * 128 + tid) * 4;
        float4 g4 = *(const float4*)(gamma + c0);
        float4 b4 = *(const float4*)(beta + c0);
        float4 r;
        r.x = (v[i].x - mean) * rstd * g4.x + b4.x;
        r.y = (v[i].y - mean) * rstd * g4.y + b4.y;
        r.z = (v[i].z - mean) * rstd * g4.z + b4.z;
        r.w = (v[i].w - mean) * rstd * g4.w + b4.w;
        if (RELU) {
            r.x = fmaxf(r.x, 0.f); r.y = fmaxf(r.y, 0.f);
            r.z = fmaxf(r.z, 0.f); r.w = fmaxf(r.w, 0.f);
        }
        r.x = __uint_as_float(cvt_tf32(r.x));
        r.y = __uint_as_float(cvt_tf32(r.y));
        r.z = __uint_as_float(cvt_tf32(r.z));
        r.w = __uint_as_float(cvt_tf32(r.w));
        op[i * 128 + tid] = r;
    }
}

// ---------------- decide scan ----------------
__global__ void decide_kernel(const float* __restrict__ rnd,
                              const void* __restrict__ maskv,
                              unsigned char* __restrict__ apply) {
    int b = threadIdx.x;
    if (b >= NB) return;
    unsigned int w0 = ((const unsigned int*)maskv)[0];
    int enc = (w0 == 0x01010101u) ? 0 : (w0 == 0x3F800000u) ? 2 : (w0 == 1u) ? 1 : 0;
    const unsigned char* m8 = (const unsigned char*)maskv;
    const int* m32 = (const int*)maskv;
    const float* mf = (const float*)maskv;
    long base = (long)b * NS_SEQ;
    int last = -1000000000;
    int cons = 0;
    for (int pos = 0; pos < NS_SEQ; pos++) {
        float r = rnd[base + pos];
        long i = base + pos;
        bool m = (enc == 0) ? (m8[i] != 0) : (enc == 1) ? (m32[i] != 0) : (mf[i] != 0.0f);
        bool iok = (pos == 0) || (pos - last >= 2);
        bool ap = m && (r < 0.5f) && iok && (cons < 2);
        last = ap ? pos : last;
        cons = ap ? cons + 1 : (m ? 0 : cons);
        apply[i] = ap ? (unsigned char)1 : (unsigned char)0;
    }
}

// ================= tf32 mma GEMM: cp.async 4-stage pipeline =================
// Inputs (A and W) are pre-rounded to tf32 bits by producers -> no in-kernel cvt.
#define SROW 36
#define STAGE_BYTES 18432            // 128*36*4
#define PAIR_BYTES 36864
#define GEMM_SMEM (4 * PAIR_BYTES)   // 147456

__device__ __forceinline__ void mma8(float* c, const uint32_t* a, const uint32_t* b) {
    asm volatile("mma.sync.aligned.m16n8k8.row.col.f32.tf32.tf32.f32 "
                 "{%0,%1,%2,%3}, {%4,%5,%6,%7}, {%8,%9}, {%0,%1,%2,%3};"
                 : "+f"(c[0]), "+f"(c[1]), "+f"(c[2]), "+f"(c[3])
                 : "r"(a[0]), "r"(a[1]), "r"(a[2]), "r"(a[3]), "r"(b[0]), "r"(b[1]));
}
__device__ __forceinline__ void ldsm4(uint32_t* r, uint32_t addr) {
    asm volatile("ldmatrix.sync.aligned.m8n8.x4.shared.b16 {%0,%1,%2,%3}, [%4];"
                 : "=r"(r[0]), "=r"(r[1]), "=r"(r[2]), "=r"(r[3]) : "r"(addr));
}
__device__ __forceinline__ void cpa16(uint32_t dst, const float* src) {
    asm volatile("cp.async.ca.shared.global [%0], [%1], 16;" :: "r"(dst), "l"(src));
}

template <int MODE>
__global__ __launch_bounds__(256) void tf32_gemm_kernel(
    const float* __restrict__ A1, const float* __restrict__ A2, int Ksplit, int K,
    const float* __restrict__ W, const float* __restrict__ bias,
    float* __restrict__ C, int N,
    const unsigned char* __restrict__ apply, const float* __restrict__ xn) {
    extern __shared__ char smem[];
    const uint32_t sb = (uint32_t)__cvta_generic_to_shared(smem);

    const int tid = threadIdx.x;
    const int wid = tid >> 5;
    const int lane = tid & 31;
    const int m0 = blockIdx.y * 128, n0 = blockIdx.x * 128;
    const int lda2 = K - Ksplit;
    const int warp_m = wid & 1, warp_n = wid >> 1;
    const int g4 = lane >> 2;
    const int t4 = lane & 3;

    const int lrow = tid >> 1;
    const int lhalf = tid & 1;
    const uint32_t dstoff = (uint32_t)(lrow * 144 + lhalf * 64);

    const uint32_t a_frag = sb + (uint32_t)(warp_m * 64 + (lane & 15)) * 144u
                          + (uint32_t)(lane >> 4) * 16u;
    const uint32_t b_frag = sb + STAGE_BYTES
                          + (uint32_t)(warp_n * 32 + (lane & 7) + ((lane >> 4) << 3)) * 144u
                          + (uint32_t)((lane >> 3) & 1) * 16u;

    const int NT = K >> 5;

    // issue one stage's loads (8 x 16B per thread)
    auto load_stage = [&](int t, int s) {
        const int gc = (t << 5) + (lhalf << 4);
        const float* asrc = (gc < Ksplit) ? (A1 + (long)(m0 + lrow) * Ksplit + gc)
                                          : (A2 + (long)(m0 + lrow) * lda2 + (gc - Ksplit));
        const float* bsrc = W + (long)(n0 + lrow) * K + gc;
        uint32_t ad = sb + (uint32_t)s * PAIR_BYTES + dstoff;
        uint32_t bd = ad + STAGE_BYTES;
#pragma unroll
        for (int q = 0; q < 4; q++) {
            cpa16(ad + q * 16, asrc + q * 4);
            cpa16(bd + q * 16, bsrc + q * 4);
        }
        asm volatile("cp.async.commit_group;" ::: "memory");
    };

    float acc[4][4][4];
#pragma unroll
    for (int i = 0; i < 4; i++)
#pragma unroll
        for (int j = 0; j < 4; j++)
#pragma unroll
            for (int u = 0; u < 4; u++) acc[i][j][u] = 0.f;

    load_stage(0, 0);
    load_stage(1, 1);

    for (int t = 0; t < NT; t++) {
        if (t + 2 < NT) load_stage(t + 2, (t + 2) & 3);
        else asm volatile("cp.async.commit_group;" ::: "memory");
        asm volatile("cp.async.wait_group 2;" ::: "memory");
        __syncthreads();

        const uint32_t so = (uint32_t)(t & 3) * PAIR_BYTES;
#pragma unroll
        for (int ks = 0; ks < 4; ks++) {
            uint32_t afr[4][4], bfr[4][2];
            const uint32_t kqb = (uint32_t)(ks * 32) + so;
#pragma unroll
            for (int i = 0; i < 4; i++)
                ldsm4(afr[i], a_frag + (uint32_t)(i * 16 * 144) + kqb);
#pragma unroll
            for (int p = 0; p < 2; p++) {
                uint32_t br[4];
                ldsm4(br, b_frag + (uint32_t)(p * 16 * 144) + kqb);
                bfr[2 * p][0] = br[0]; bfr[2 * p][1] = br[1];
                bfr[2 * p + 1][0] = br[2]; bfr[2 * p + 1][1] = br[3];
            }
#pragma unroll
            for (int i = 0; i < 4; i++)
#pragma unroll
                for (int j = 0; j < 4; j++) mma8(acc[i][j], afr[i], bfr[j]);
        }
    }

    // epilogue
#pragma unroll
    for (int i = 0; i < 4; i++) {
        long r0 = m0 + warp_m * 64 + i * 16 + g4;
        long r1 = r0 + 8;
        unsigned char ap0 = 0, ap1 = 0;
        if (MODE == 1) { ap0 = apply[r0]; ap1 = apply[r1]; }
#pragma unroll
        for (int j = 0; j < 4; j++) {
            int c = n0 + warp_n * 32 + j * 8 + 2 * t4;
            float v00 = acc[i][j][0] + bias[c];
            float v01 = acc[i][j][1] + bias[c + 1];
            float v10 = acc[i][j][2] + bias[c];
            float v11 = acc[i][j][3] + bias[c + 1];
            if (MODE == 0) {
                *(float2*)(C + r0 * (long)N + c) = make_float2(v00, v01);
                *(float2*)(C + r1 * (long)N + c) = make_float2(v10, v11);
            } else {
                float2 x0 = *(const float2*)(xn + r0 * 512 + c);
                float2 x1 = *(const float2*)(xn + r1 * 512 + c);
                float p00, p01, p10, p11;
                if (c < 256)      { p00 = fminf(fmaxf(v00, 0.f), 1.f); p10 = fminf(fmaxf(v10, 0.f), 1.f); }
                else if (c < 384) { p00 = v00 * 0.3f; p10 = v10 * 0.3f; }
                else if (c < 448) { p00 = v00 * 0.7f; p10 = v10 * 0.7f; }
                else              { p00 = v00 + 0.05f; p10 = v10 + 0.05f; }
                int c1 = c + 1;
                if (c1 < 256)      { p01 = fminf(fmaxf(v01, 0.f), 1.f); p11 = fminf(fmaxf(v11, 0.f), 1.f); }
                else if (c1 < 384) { p01 = v01 * 0.3f; p11 = v11 * 0.3f; }
                else if (c1 < 448) { p01 = v01 * 0.7f; p11 = v11 * 0.7f; }
                else               { p01 = v01 + 0.05f; p11 = v11 + 0.05f; }
                *(float2*)(C + r0 * 512 + c) = make_float2(ap0 ? p00 : x0.x, ap0 ? p01 : x0.y);
                *(float2*)(C + r1 * 512 + c) = make_float2(ap1 ? p10 : x1.x, ap1 ? p11 : x1.y);
            }
        }
    }
}

// ================= BiLSTM recurrence: R13 v7 VERBATIM (proven 12,509) =================
__device__ __forceinline__ void cluster_sync_() {
    asm volatile("barrier.cluster.arrive.aligned;" ::: "memory");
    asm volatile("barrier.cluster.wait.aligned;" ::: "memory");
}

__global__ __launch_bounds__(256, 1) __cluster_dims__(8, 1, 1)
void lstm_kernel(const float* __restrict__ zx, const float* __restrict__ whh,
                 float* __restrict__ hout) {
    __shared__ float hbuf[2][2][272];
    __shared__ float4 zredv[2][32];
    __shared__ float hstage[8][2][32];

    const int rank = blockIdx.x & 7;
    const int cl = blockIdx.x >> 3;
    const int dir = cl >> 3;
    const int bp = cl & 7;
    const int tid = threadIdx.x;
    const int wid = tid >> 5;
    const int lane = tid & 31;
    const int g4 = lane >> 2;
    const int t4 = lane & 3;

    const int cr0 = wid * 16 + g4;
    const int zrowA = ((cr0 >> 5) << 8) + rank * 32 + (cr0 & 31);
    const int zrowB = (((cr0 + 8) >> 5) << 8) + rank * 32 + ((cr0 + 8) & 31);
    const int gA = cr0 >> 5, uA = cr0 & 31;
    const int gB = (cr0 + 8) >> 5, uB = (cr0 + 8) & 31;

    uint32_t wA[32][4];
    {
        const float* w0p = whh + ((long)dir * 1024 + zrowA) * 256;
        const float* w1p = whh + ((long)dir * 1024 + zrowB) * 256;
#pragma unroll
        for (int q = 0; q < 32; q++) {
            int k0 = q * 8 + t4;
            wA[q][0] = cvt_tf32(w0p[k0]);
            wA[q][1] = cvt_tf32(w1p[k0]);
            wA[q][2] = cvt_tf32(w0p[k0 + 4]);
            wA[q][3] = cvt_tf32(w1p[k0 + 4]);
        }
    }

    for (int i = tid; i < 2 * 2 * 272; i += 256) (&hbuf[0][0][0])[i] = 0.f;
    __syncthreads();
    cluster_sync_();

    float cst = 0.f;
    const int gu = tid & 31;
    const int gb = tid >> 5;
    const long nb0 = (long)(bp * 2) * NS_SEQ;
    const long nb1 = (long)(bp * 2 + 1) * NS_SEQ;

    const long zc0 = (long)dir * 1024 + zrowA;
    const long zc1 = (long)dir * 1024 + zrowB;
    const int bb = g4 & 1;

    uint32_t rA[8];
    if (tid < 64) {
        const int guG = rank * 32 + gu;
        const int off = ((guG >> 6) * 68) + (guG & 63);
        uint32_t laddr = (uint32_t)__cvta_generic_to_shared(&hbuf[0][gb][off]);
#pragma unroll
        for (int p = 0; p < 8; p++)
            asm("mapa.shared::cluster.u32 %0, %1, %2;" : "=r"(rA[p]) : "r"(laddr), "r"(p));
    }

    float zx00 = 0, zx01 = 0, zx10 = 0, zx11 = 0;
    if (t4 == 0) {
        int s0 = dir ? (NS_SEQ - 1) : 0;
        zx00 = zx[(nb0 + s0) * 2048 + zc0];
        zx01 = zx[(nb1 + s0) * 2048 + zc0];
        zx10 = zx[(nb0 + s0) * 2048 + zc1];
        zx11 = zx[(nb1 + s0) * 2048 + zc1];
    }

    int buf = 0;
    for (int t = 0; t < NS_SEQ; t++) {
        float nx00 = 0, nx01 = 0, nx10 = 0, nx11 = 0;
        if (t4 == 0 && t < NS_SEQ - 1) {
            int sn = dir ? (NS_SEQ - 2 - t) : (t + 1);
            nx00 = zx[(nb0 + sn) * 2048 + zc0];
            nx01 = zx[(nb1 + sn) * 2048 + zc0];
            nx10 = zx[(nb0 + sn) * 2048 + zc1];
            nx11 = zx[(nb1 + sn) * 2048 + zc1];
        }

        float ca[4] = {0, 0, 0, 0}, cb[4] = {0, 0, 0, 0};
        float cc[4] = {0, 0, 0, 0}, cd[4] = {0, 0, 0, 0};
        const float* hb = &hbuf[buf][bb][0];
#pragma unroll
        for (int q = 0; q < 32; q += 4) {
            uint32_t b0[2], b1[2], b2[2], b3[2];
            {
                int k = q * 8 + t4;
                b0[0] = __float_as_uint(hb[((k >> 6) * 68) + (k & 63)]);
                int k2 = k + 4;
                b0[1] = __float_as_uint(hb[((k2 >> 6) * 68) + (k2 & 63)]);
                k = (q + 1) * 8 + t4;
                b1[0] = __float_as_uint(hb[((k >> 6) * 68) + (k & 63)]);
                k2 = k + 4;
                b1[1] = __float_as_uint(hb[((k2 >> 6) * 68) + (k2 & 63)]);
                k = (q + 2) * 8 + t4;
                b2[0] = __float_as_uint(hb[((k >> 6) * 68) + (k & 63)]);
                k2 = k + 4;
                b2[1] = __float_as_uint(hb[((k2 >> 6) * 68) + (k2 & 63)]);
                k = (q + 3) * 8 + t4;
                b3[0] = __float_as_uint(hb[((k >> 6) * 68) + (k & 63)]);
                k2 = k + 4;
                b3[1] = __float_as_uint(hb[((k2 >> 6) * 68) + (k2 & 63)]);
            }
            mma8(ca, wA[q], b0);
            mma8(cb, wA[q + 1], b1);
            mma8(cc, wA[q + 2], b2);
            mma8(cd, wA[q + 3], b3);
        }

        if (t4 == 0) {
            ((float*)&zredv[0][uA])[gA] = ca[0] + cb[0] + cc[0] + cd[0] + zx00;
            ((float*)&zredv[1][uA])[gA] = ca[1] + cb[1] + cc[1] + cd[1] + zx01;
            ((float*)&zredv[0][uB])[gB] = ca[2] + cb[2] + cc[2] + cd[2] + zx10;
            ((float*)&zredv[1][uB])[gB] = ca[3] + cb[3] + cc[3] + cd[3] + zx11;
        }
        __syncthreads();

        if (tid < 64) {
            float4 z4 = zredv[gb][gu];
            float ig = fsig(z4.x), fg = fsig(z4.y), gg = ftanh_(z4.z), og = fsig(z4.w);
            cst = fg * cst + ig * gg;
            float h = og * ftanh_(cst);
            float hr = __uint_as_float(cvt_tf32(h));
            const uint32_t bo = (uint32_t)(buf ^ 1) * 2176u;
#pragma unroll
            for (int p = 0; p < 8; p++)
                asm volatile("st.shared::cluster.f32 [%0], %1;" :: "r"(rA[p] + bo), "f"(hr) : "memory");
            hstage[t & 7][gb][gu] = hr;
        }

        if ((t & 7) == 7) {
            __syncthreads();
            const int obase = dir * 256 + rank * 32;
            for (int idx = tid; idx < 512; idx += 256) {
                int j = idx >> 6;
                int r = idx & 63;
                int b = r >> 5, u = r & 31;
                int tb = t - 7 + j;
                int sj = dir ? (NS_SEQ - 1 - tb) : tb;
                const long nb = b ? nb1 : nb0;
                hout[(nb + sj) * 512 + obase + u] = hstage[j][b][u];
            }
            __syncthreads();
        }
        cluster_sync_();
        buf ^= 1;
        zx00 = nx00; zx01 = nx01; zx10 = nx10; zx11 = nx11;
    }
}

// ---------------- launch ----------------
extern "C" void kernel_launch(void* const* d_in, const int* in_sizes, int n_in,
                              void* d_out, int out_size) {
    const float* features = (const float*)d_in[0];
    const void* mask = d_in[1];
    const float* rnd = (const float*)d_in[2];
    const float* ln_g = (const float*)d_in[3];
    const float* ln_b = (const float*)d_in[4];
    const float* Wih0 = (const float*)d_in[5];
    const float* Whh0 = (const float*)d_in[6];
    const float* b0 = (const float*)d_in[7];
    const float* Wih1 = (const float*)d_in[8];
    const float* Whh1 = (const float*)d_in[9];
    const float* b1 = (const float*)d_in[10];
    const float* gW1 = (const float*)d_in[11];
    const float* gb1 = (const float*)d_in[12];
    const float* gln_g = (const float*)d_in[13];
    const float* gln_b = (const float*)d_in[14];
    const float* gW2 = (const float*)d_in[15];
    const float* gb2 = (const float*)d_in[16];
    float* out = (float*)d_out;

    float *xn, *zx, *h1, *h2, *gpre, *wtf;
    unsigned char* apl;
    cudaGetSymbolAddress((void**)&xn, g_xn);
    cudaGetSymbolAddress((void**)&zx, g_zx);
    cudaGetSymbolAddress((void**)&h1, g_h1);
    cudaGetSymbolAddress((void**)&h2, g_h2);
    cudaGetSymbolAddress((void**)&gpre, g_gpre);
    cudaGetSymbolAddress((void**)&apl, g_apply);
    cudaGetSymbolAddress((void**)&wtf, g_wtf);
    float* Wih0c = wtf;
    float* Wih1c = wtf + 1048576;
    float* gW1c = wtf + 3145728;
    float* gW2c = wtf + 4194304;

    cudaFuncSetAttribute(tf32_gemm_kernel<0>, cudaFuncAttributeMaxDynamicSharedMemorySize, GEMM_SMEM);
    cudaFuncSetAttribute(tf32_gemm_kernel<1>, cudaFuncAttributeMaxDynamicSharedMemorySize, GEMM_SMEM);

    // 0. tf32-round weights into scratch
    cvtw_kernel<<<4096, 256>>>(Wih0, Wih0c, 1048576);
    cvtw_kernel<<<8192, 256>>>(Wih1, Wih1c, 2097152);
    cvtw_kernel<<<4096, 256>>>(gW1, gW1c, 1048576);
    cvtw_kernel<<<4096, 256>>>(gW2, gW2c, 1048576);
    // 1. LayerNorm(features) -> xn (tf32-rounded)
    ln_kernel<512, false><<<NROWS, 128>>>(features, xn, ln_g, ln_b);
    // 2. decide scan -> apply
    decide_kernel<<<1, 32>>>(rnd, mask, apl);
    // 3. layer0 input projections: zx = xn @ Wih0cat^T + b0   [32768 x 2048]
    tf32_gemm_kernel<0><<<dim3(16, 256), 256, GEMM_SMEM>>>(xn, xn, 512, 512, Wih0c, b0, zx, 2048, nullptr, nullptr);
    // 4. layer0 recurrence -> h1
    lstm_kernel<<<128, 256>>>(zx, Whh0, h1);
    // 5. layer1 input projections: zx = h1 @ Wih1cat^T + b1
    tf32_gemm_kernel<0><<<dim3(16, 256), 256, GEMM_SMEM>>>(h1, h1, 512, 512, Wih1c, b1, zx, 2048, nullptr, nullptr);
    // 6. layer1 recurrence -> h2
    lstm_kernel<<<128, 256>>>(zx, Whh1, h2);
    // 7. gpre = [xn | h2] @ gW1^T + gb1   [32768 x 1024]
    tf32_gemm_kernel<0><<<dim3(8, 256), 256, GEMM_SMEM>>>(xn, h2, 512, 1024, gW1c, gb1, gpre, 1024, nullptr, nullptr);
    // 8. LN + ReLU in place (tf32-rounded)
    ln_kernel<1024, true><<<NROWS, 128>>>(gpre, gpre, gln_g, gln_b);
    // 9. orn (first 512 cols of gW2) + ornament transform + apply-select -> out
    tf32_gemm_kernel<1><<<dim3(4, 256), 256, GEMM_SMEM>>>(gpre, gpre, 1024, 1024, gW2c, gb2, out, 512, apl, xn);
}

// round 16
// speedup vs baseline: 1.1999x; 1.0784x over previous
#include <cuda_runtime.h>
#include <cstdint>

// Problem dims
#define NB 16
#define NS_SEQ 2048
#define ND 512
#define NH 256
#define NROWS 32768   // NB*NS_SEQ
#define NHID 1024

// ---------------- scratch (static device memory; no allocations) ----------------
__device__ float g_xn[(long)NROWS * ND];
__device__ float g_zx[(long)NROWS * 2048];
__device__ float g_h1[(long)NROWS * ND];
__device__ float g_h2[(long)NROWS * ND];
__device__ float g_gpre[(long)NROWS * NHID];
__device__ unsigned char g_apply[NROWS];
__device__ float g_wtf[5242880];   // tf32-rounded weights: Wih0|Wih1|gW1|gW2

// ---------------- helpers ----------------
__device__ __forceinline__ float ftanh_(float x) {
    float r; asm("tanh.approx.f32 %0, %1;" : "=f"(r) : "f"(x)); return r;
}
__device__ __forceinline__ float fsig(float x) {
    return 0.5f * ftanh_(0.5f * x) + 0.5f;
}
__device__ __forceinline__ uint32_t cvt_tf32(float x) {
    uint32_t r; asm("cvt.rn.tf32.f32 %0, %1;" : "=r"(r) : "f"(x)); return r;
}

// ---------------- weight tf32 pre-round ----------------
__global__ void cvtw_kernel(const float* __restrict__ src, float* __restrict__ dst, int n) {
    int i = blockIdx.x * 256 + threadIdx.x;
    if (i < n) dst[i] = __uint_as_float(cvt_tf32(src[i]));
}

// ---------------- LayerNorm (outputs tf32-rounded: they feed GEMM A operands) ----------------
template <int COLS, bool RELU>
__global__ __launch_bounds__(128) void ln_kernel(const float* __restrict__ in,
                                                 float* __restrict__ out,
                                                 const float* __restrict__ gamma,
                                                 const float* __restrict__ beta) {
    constexpr int V = COLS / 512;
    long row = blockIdx.x;
    const float4* ip = (const float4*)(in + row * (long)COLS);
    int tid = threadIdx.x;
    float4 v[V];
    float s = 0.f, ss = 0.f;
#pragma unroll
    for (int i = 0; i < V; i++) {
        v[i] = ip[i * 128 + tid];
        s += v[i].x + v[i].y + v[i].z + v[i].w;
        ss += v[i].x * v[i].x + v[i].y * v[i].y + v[i].z * v[i].z + v[i].w * v[i].w;
    }
#pragma unroll
    for (int o = 16; o > 0; o >>= 1) {
        s += __shfl_xor_sync(0xffffffffu, s, o);
        ss += __shfl_xor_sync(0xffffffffu, ss, o);
    }
    __shared__ float red[8];
    int wid = tid >> 5;
    if ((tid & 31) == 0) { red[wid] = s; red[4 + wid] = ss; }
    __syncthreads();
    s = red[0] + red[1] + red[2] + red[3];
    ss = red[4] + red[5] + red[6] + red[7];
    float mean = s * (1.0f / COLS);
    float var = ss * (1.0f / COLS) - mean * mean;
    float rstd = rsqrtf(var + 1e-5f);
    float4* op = (float4*)(out + row * (long)COLS);
#pragma unroll
    for (int i = 0; i < V; i++) {
        int c0 = (i * 128 + tid) * 4;
        float4 g4 = *(const float4*)(gamma + c0);
        float4 b4 = *(const float4*)(beta + c0);
        float4 r;
        r.x = (v[i].x - mean) * rstd * g4.x + b4.x;
        r.y = (v[i].y - mean) * rstd * g4.y + b4.y;
        r.z = (v[i].z - mean) * rstd * g4.z + b4.z;
        r.w = (v[i].w - mean) * rstd * g4.w + b4.w;
        if (RELU) {
            r.x = fmaxf(r.x, 0.f); r.y = fmaxf(r.y, 0.f);
            r.z = fmaxf(r.z, 0.f); r.w = fmaxf(r.w, 0.f);
        }
        r.x = __uint_as_float(cvt_tf32(r.x));
        r.y = __uint_as_float(cvt_tf32(r.y));
        r.z = __uint_as_float(cvt_tf32(r.z));
        r.w = __uint_as_float(cvt_tf32(r.w));
        op[i * 128 + tid] = r;
    }
}

// ---------------- decide scan ----------------
__global__ void decide_kernel(const float* __restrict__ rnd,
                              const void* __restrict__ maskv,
                              unsigned char* __restrict__ apply) {
    int b = threadIdx.x;
    if (b >= NB) return;
    unsigned int w0 = ((const unsigned int*)maskv)[0];
    int enc = (w0 == 0x01010101u) ? 0 : (w0 == 0x3F800000u) ? 2 : (w0 == 1u) ? 1 : 0;
    const unsigned char* m8 = (const unsigned char*)maskv;
    const int* m32 = (const int*)maskv;
    const float* mf = (const float*)maskv;
    long base = (long)b * NS_SEQ;
    int last = -1000000000;
    int cons = 0;
    for (int pos = 0; pos < NS_SEQ; pos++) {
        float r = rnd[base + pos];
        long i = base + pos;
        bool m = (enc == 0) ? (m8[i] != 0) : (enc == 1) ? (m32[i] != 0) : (mf[i] != 0.0f);
        bool iok = (pos == 0) || (pos - last >= 2);
        bool ap = m && (r < 0.5f) && iok && (cons < 2);
        last = ap ? pos : last;
        cons = ap ? cons + 1 : (m ? 0 : cons);
        apply[i] = ap ? (unsigned char)1 : (unsigned char)0;
    }
}

// ================= tf32 mma GEMM: cp.async 4-stage pipeline (R15, passing) =================
#define SROW 36
#define STAGE_BYTES 18432
#define PAIR_BYTES 36864
#define GEMM_SMEM (4 * PAIR_BYTES)

__device__ __forceinline__ void mma8(float* c, const uint32_t* a, const uint32_t* b) {
    asm volatile("mma.sync.aligned.m16n8k8.row.col.f32.tf32.tf32.f32 "
                 "{%0,%1,%2,%3}, {%4,%5,%6,%7}, {%8,%9}, {%0,%1,%2,%3};"
                 : "+f"(c[0]), "+f"(c[1]), "+f"(c[2]), "+f"(c[3])
                 : "r"(a[0]), "r"(a[1]), "r"(a[2]), "r"(a[3]), "r"(b[0]), "r"(b[1]));
}
__device__ __forceinline__ void ldsm4(uint32_t* r, uint32_t addr) {
    asm volatile("ldmatrix.sync.aligned.m8n8.x4.shared.b16 {%0,%1,%2,%3}, [%4];"
                 : "=r"(r[0]), "=r"(r[1]), "=r"(r[2]), "=r"(r[3]) : "r"(addr));
}
__device__ __forceinline__ void cpa16(uint32_t dst, const float* src) {
    asm volatile("cp.async.ca.shared.global [%0], [%1], 16;" :: "r"(dst), "l"(src));
}

template <int MODE>
__global__ __launch_bounds__(256) void tf32_gemm_kernel(
    const float* __restrict__ A1, const float* __restrict__ A2, int Ksplit, int K,
    const float* __restrict__ W, const float* __restrict__ bias,
    float* __restrict__ C, int N,
    const unsigned char* __restrict__ apply, const float* __restrict__ xn) {
    extern __shared__ char smem[];
    const uint32_t sb = (uint32_t)__cvta_generic_to_shared(smem);

    const int tid = threadIdx.x;
    const int wid = tid >> 5;
    const int lane = tid & 31;
    const int m0 = blockIdx.y * 128, n0 = blockIdx.x * 128;
    const int lda2 = K - Ksplit;
    const int warp_m = wid & 1, warp_n = wid >> 1;
    const int g4 = lane >> 2;
    const int t4 = lane & 3;

    const int lrow = tid >> 1;
    const int lhalf = tid & 1;
    const uint32_t dstoff = (uint32_t)(lrow * 144 + lhalf * 64);

    const uint32_t a_frag = sb + (uint32_t)(warp_m * 64 + (lane & 15)) * 144u
                          + (uint32_t)(lane >> 4) * 16u;
    const uint32_t b_frag = sb + STAGE_BYTES
                          + (uint32_t)(warp_n * 32 + (lane & 7) + ((lane >> 4) << 3)) * 144u
                          + (uint32_t)((lane >> 3) & 1) * 16u;

    const int NT = K >> 5;

    auto load_stage = [&](int t, int s) {
        const int gc = (t << 5) + (lhalf << 4);
        const float* asrc = (gc < Ksplit) ? (A1 + (long)(m0 + lrow) * Ksplit + gc)
                                          : (A2 + (long)(m0 + lrow) * lda2 + (gc - Ksplit));
        const float* bsrc = W + (long)(n0 + lrow) * K + gc;
        uint32_t ad = sb + (uint32_t)s * PAIR_BYTES + dstoff;
        uint32_t bd = ad + STAGE_BYTES;
#pragma unroll
        for (int q = 0; q < 4; q++) {
            cpa16(ad + q * 16, asrc + q * 4);
            cpa16(bd + q * 16, bsrc + q * 4);
        }
        asm volatile("cp.async.commit_group;" ::: "memory");
    };

    float acc[4][4][4];
#pragma unroll
    for (int i = 0; i < 4; i++)
#pragma unroll
        for (int j = 0; j < 4; j++)
#pragma unroll
            for (int u = 0; u < 4; u++) acc[i][j][u] = 0.f;

    load_stage(0, 0);
    load_stage(1, 1);

    for (int t = 0; t < NT; t++) {
        if (t + 2 < NT) load_stage(t + 2, (t + 2) & 3);
        else asm volatile("cp.async.commit_group;" ::: "memory");
        asm volatile("cp.async.wait_group 2;" ::: "memory");
        __syncthreads();

        const uint32_t so = (uint32_t)(t & 3) * PAIR_BYTES;
#pragma unroll
        for (int ks = 0; ks < 4; ks++) {
            uint32_t afr[4][4], bfr[4][2];
            const uint32_t kqb = (uint32_t)(ks * 32) + so;
#pragma unroll
            for (int i = 0; i < 4; i++)
                ldsm4(afr[i], a_frag + (uint32_t)(i * 16 * 144) + kqb);
#pragma unroll
            for (int p = 0; p < 2; p++) {
                uint32_t br[4];
                ldsm4(br, b_frag + (uint32_t)(p * 16 * 144) + kqb);
                bfr[2 * p][0] = br[0]; bfr[2 * p][1] = br[1];
                bfr[2 * p + 1][0] = br[2]; bfr[2 * p + 1][1] = br[3];
            }
#pragma unroll
            for (int i = 0; i < 4; i++)
#pragma unroll
                for (int j = 0; j < 4; j++) mma8(acc[i][j], afr[i], bfr[j]);
        }
    }

#pragma unroll
    for (int i = 0; i < 4; i++) {
        long r0 = m0 + warp_m * 64 + i * 16 + g4;
        long r1 = r0 + 8;
        unsigned char ap0 = 0, ap1 = 0;
        if (MODE == 1) { ap0 = apply[r0]; ap1 = apply[r1]; }
#pragma unroll
        for (int j = 0; j < 4; j++) {
            int c = n0 + warp_n * 32 + j * 8 + 2 * t4;
            float v00 = acc[i][j][0] + bias[c];
            float v01 = acc[i][j][1] + bias[c + 1];
            float v10 = acc[i][j][2] + bias[c];
            float v11 = acc[i][j][3] + bias[c + 1];
            if (MODE == 0) {
                *(float2*)(C + r0 * (long)N + c) = make_float2(v00, v01);
                *(float2*)(C + r1 * (long)N + c) = make_float2(v10, v11);
            } else {
                float2 x0 = *(const float2*)(xn + r0 * 512 + c);
                float2 x1 = *(const float2*)(xn + r1 * 512 + c);
                float p00, p01, p10, p11;
                if (c < 256)      { p00 = fminf(fmaxf(v00, 0.f), 1.f); p10 = fminf(fmaxf(v10, 0.f), 1.f); }
                else if (c < 384) { p00 = v00 * 0.3f; p10 = v10 * 0.3f; }
                else if (c < 448) { p00 = v00 * 0.7f; p10 = v10 * 0.7f; }
                else              { p00 = v00 + 0.05f; p10 = v10 + 0.05f; }
                int c1 = c + 1;
                if (c1 < 256)      { p01 = fminf(fmaxf(v01, 0.f), 1.f); p11 = fminf(fmaxf(v11, 0.f), 1.f); }
                else if (c1 < 384) { p01 = v01 * 0.3f; p11 = v11 * 0.3f; }
                else if (c1 < 448) { p01 = v01 * 0.7f; p11 = v11 * 0.7f; }
                else               { p01 = v01 + 0.05f; p11 = v11 + 0.05f; }
                *(float2*)(C + r0 * 512 + c) = make_float2(ap0 ? p00 : x0.x, ap0 ? p01 : x0.y);
                *(float2*)(C + r1 * 512 + c) = make_float2(ap1 ? p10 : x1.x, ap1 ? p11 : x1.y);
            }
        }
    }
}

// ================= BiLSTM recurrence v9: dual-chain latency hiding =================
// 8 clusters x 8 CTAs (64 SMs). Each cluster runs TWO chains (same dir -> same
// Whh regs): chain c handles batch-pair bp = 2*grp + c. Phases alternate A/B;
// schedule per phase: arrive -> compute (MMA+gates) -> wait -> remote stores.
// The cluster-barrier latency for phase p overlaps phase p's compute; phase p's
// stores are released by arrive_{p+1}, acquired by wait_{p+1}, read in p+2
// (same chain). zredv double-buffered by chain parity; hbuf slot parity per
// chain-step; compute body = R13's proven kernel.

__global__ __launch_bounds__(256, 1) __cluster_dims__(8, 1, 1)
void lstm_kernel(const float* __restrict__ zx, const float* __restrict__ whh,
                 float* __restrict__ hout) {
    __shared__ float hbuf[2][2][2][272];     // [chain][slot][batch][272]
    __shared__ float4 zredv[2][2][32];       // [chain][batch][unit]
    __shared__ float hstage[2][8][2][32];    // [chain][step&7][batch][unit]

    const int rank = blockIdx.x & 7;
    const int cl = blockIdx.x >> 3;          // 0..7
    const int dir = cl >> 2;
    const int grp = cl & 3;
    const int tid = threadIdx.x;
    const int wid = tid >> 5;
    const int lane = tid & 31;
    const int g4 = lane >> 2;
    const int t4 = lane & 3;

    const int cr0 = wid * 16 + g4;
    const int zrowA = ((cr0 >> 5) << 8) + rank * 32 + (cr0 & 31);
    const int zrowB = (((cr0 + 8) >> 5) << 8) + rank * 32 + ((cr0 + 8) & 31);
    const int gA = cr0 >> 5, uA = cr0 & 31;
    const int gB = (cr0 + 8) >> 5, uB = (cr0 + 8) & 31;

    uint32_t wA[32][4];
    {
        const float* w0p = whh + ((long)dir * 1024 + zrowA) * 256;
        const float* w1p = whh + ((long)dir * 1024 + zrowB) * 256;
#pragma unroll
        for (int q = 0; q < 32; q++) {
            int k0 = q * 8 + t4;
            wA[q][0] = cvt_tf32(w0p[k0]);
            wA[q][1] = cvt_tf32(w1p[k0]);
            wA[q][2] = cvt_tf32(w0p[k0 + 4]);
            wA[q][3] = cvt_tf32(w1p[k0 + 4]);
        }
    }

    for (int i = tid; i < 2 * 2 * 2 * 272; i += 256) (&hbuf[0][0][0][0])[i] = 0.f;
    __syncthreads();
    asm volatile("barrier.cluster.arrive.aligned;" ::: "memory");
    asm volatile("barrier.cluster.wait.aligned;" ::: "memory");

    const int gu = tid & 31;
    const int gb = tid >> 5;
    const long zc0 = (long)dir * 1024 + zrowA;
    const long zc1 = (long)dir * 1024 + zrowB;
    const int bb = g4 & 1;

    // remote store addresses for chain 0 slot 0 (chain/slot byte offsets added in-loop)
    uint32_t rA[8];
    if (tid < 64) {
        const int guG = rank * 32 + gu;
        const int off = ((guG >> 6) * 68) + (guG & 63);
        uint32_t laddr = (uint32_t)__cvta_generic_to_shared(&hbuf[0][0][gb][off]);
#pragma unroll
        for (int p = 0; p < 8; p++)
            asm("mapa.shared::cluster.u32 %0, %1, %2;" : "=r"(rA[p]) : "r"(laddr), "r"(p));
    }

    const long nbA0 = (long)((2 * grp) * 2) * NS_SEQ;
    const long nbA1 = nbA0 + NS_SEQ;
    const long nbB0 = (long)((2 * grp + 1) * 2) * NS_SEQ;
    const long nbB1 = nbB0 + NS_SEQ;

    float cstA = 0.f, cstB = 0.f;
    float ax00 = 0, ax01 = 0, ax10 = 0, ax11 = 0;
    float bx00 = 0, bx01 = 0, bx10 = 0, bx11 = 0;
    if (t4 == 0) {
        int s0 = dir ? (NS_SEQ - 1) : 0;
        ax00 = zx[(nbA0 + s0) * 2048 + zc0];
        ax01 = zx[(nbA1 + s0) * 2048 + zc0];
        ax10 = zx[(nbA0 + s0) * 2048 + zc1];
        ax11 = zx[(nbA1 + s0) * 2048 + zc1];
        bx00 = zx[(nbB0 + s0) * 2048 + zc0];
        bx01 = zx[(nbB1 + s0) * 2048 + zc0];
        bx10 = zx[(nbB0 + s0) * 2048 + zc1];
        bx11 = zx[(nbB1 + s0) * 2048 + zc1];
    }

    auto phase = [&](int ch, int t, float& cst, long nb0c, long nb1c,
                     float& zx00, float& zx01, float& zx10, float& zx11) {
        asm volatile("barrier.cluster.arrive.aligned;" ::: "memory");
        // prefetch next zx for this chain (2-phase slack)
        float nx00 = 0, nx01 = 0, nx10 = 0, nx11 = 0;
        if (t4 == 0 && t < NS_SEQ - 1) {
            int sn = dir ? (NS_SEQ - 2 - t) : (t + 1);
            nx00 = zx[(nb0c + sn) * 2048 + zc0];
            nx01 = zx[(nb1c + sn) * 2048 + zc0];
            nx10 = zx[(nb0c + sn) * 2048 + zc1];
            nx11 = zx[(nb1c + sn) * 2048 + zc1];
        }
        const int rslot = t & 1;

        float ca[4] = {0, 0, 0, 0}, cb[4] = {0, 0, 0, 0};
        float cc[4] = {0, 0, 0, 0}, cd[4] = {0, 0, 0, 0};
        const float* hb = &hbuf[ch][rslot][bb][0];
#pragma unroll
        for (int q = 0; q < 32; q += 4) {
            uint32_t b0[2], b1[2], b2[2], b3[2];
            {
                int k = q * 8 + t4;
                b0[0] = __float_as_uint(hb[((k >> 6) * 68) + (k & 63)]);
                int k2 = k + 4;
                b0[1] = __float_as_uint(hb[((k2 >> 6) * 68) + (k2 & 63)]);
                k = (q + 1) * 8 + t4;
                b1[0] = __float_as_uint(hb[((k >> 6) * 68) + (k & 63)]);
                k2 = k + 4;
                b1[1] = __float_as_uint(hb[((k2 >> 6) * 68) + (k2 & 63)]);
                k = (q + 2) * 8 + t4;
                b2[0] = __float_as_uint(hb[((k >> 6) * 68) + (k & 63)]);
                k2 = k + 4;
                b2[1] = __float_as_uint(hb[((k2 >> 6) * 68) + (k2 & 63)]);
                k = (q + 3) * 8 + t4;
                b3[0] = __float_as_uint(hb[((k >> 6) * 68) + (k & 63)]);
                k2 = k + 4;
                b3[1] = __float_as_uint(hb[((k2 >> 6) * 68) + (k2 & 63)]);
            }
            mma8(ca, wA[q], b0);
            mma8(cb, wA[q + 1], b1);
            mma8(cc, wA[q + 2], b2);
            mma8(cd, wA[q + 3], b3);
        }

        if (t4 == 0) {
            ((float*)&zredv[ch][0][uA])[gA] = ca[0] + cb[0] + cc[0] + cd[0] + zx00;
            ((float*)&zredv[ch][1][uA])[gA] = ca[1] + cb[1] + cc[1] + cd[1] + zx01;
            ((float*)&zredv[ch][0][uB])[gB] = ca[2] + cb[2] + cc[2] + cd[2] + zx10;
            ((float*)&zredv[ch][1][uB])[gB] = ca[3] + cb[3] + cc[3] + cd[3] + zx11;
        }
        __syncthreads();

        float hr = 0.f;
        if (tid < 64) {
            float4 z4 = zredv[ch][gb][gu];
            float ig = fsig(z4.x), fg = fsig(z4.y), gg = ftanh_(z4.z), og = fsig(z4.w);
            cst = fg * cst + ig * gg;
            float h = og * ftanh_(cst);
            hr = __uint_as_float(cvt_tf32(h));
        }

        // barrier completion overlapped the compute above
        asm volatile("barrier.cluster.wait.aligned;" ::: "memory");

        if (tid < 64) {
            const uint32_t co = (uint32_t)ch * 4352u + (uint32_t)(rslot ^ 1) * 2176u;
#pragma unroll
            for (int p = 0; p < 8; p++)
                asm volatile("st.shared::cluster.f32 [%0], %1;" :: "r"(rA[p] + co), "f"(hr) : "memory");
            hstage[ch][t & 7][gb][gu] = hr;
        }

        if ((t & 7) == 7) {
            __syncthreads();
            const int obase = dir * 256 + rank * 32;
            for (int idx = tid; idx < 512; idx += 256) {
                int j = idx >> 6;
                int r = idx & 63;
                int b = r >> 5, u = r & 31;
                int tb = t - 7 + j;
                int sj = dir ? (NS_SEQ - 1 - tb) : tb;
                const long nb = b ? nb1c : nb0c;
                hout[(nb + sj) * 512 + obase + u] = hstage[ch][j][b][u];
            }
            __syncthreads();
        }
        zx00 = nx00; zx01 = nx01; zx10 = nx10; zx11 = nx11;
    };

    for (int t = 0; t < NS_SEQ; t++) {
        phase(0, t, cstA, nbA0, nbA1, ax00, ax01, ax10, ax11);
        phase(1, t, cstB, nbB0, nbB1, bx00, bx01, bx10, bx11);
    }
    // final handshake: peers' last stores into our SMEM land before exit
    asm volatile("barrier.cluster.arrive.aligned;" ::: "memory");
    asm volatile("barrier.cluster.wait.aligned;" ::: "memory");
}

// ---------------- launch ----------------
extern "C" void kernel_launch(void* const* d_in, const int* in_sizes, int n_in,
                              void* d_out, int out_size) {
    const float* features = (const float*)d_in[0];
    const void* mask = d_in[1];
    const float* rnd = (const float*)d_in[2];
    const float* ln_g = (const float*)d_in[3];
    const float* ln_b = (const float*)d_in[4];
    const float* Wih0 = (const float*)d_in[5];
    const float* Whh0 = (const float*)d_in[6];
    const float* b0 = (const float*)d_in[7];
    const float* Wih1 = (const float*)d_in[8];
    const float* Whh1 = (const float*)d_in[9];
    const float* b1 = (const float*)d_in[10];
    const float* gW1 = (const float*)d_in[11];
    const float* gb1 = (const float*)d_in[12];
    const float* gln_g = (const float*)d_in[13];
    const float* gln_b = (const float*)d_in[14];
    const float* gW2 = (const float*)d_in[15];
    const float* gb2 = (const float*)d_in[16];
    float* out = (float*)d_out;

    float *xn, *zx, *h1, *h2, *gpre, *wtf;
    unsigned char* apl;
    cudaGetSymbolAddress((void**)&xn, g_xn);
    cudaGetSymbolAddress((void**)&zx, g_zx);
    cudaGetSymbolAddress((void**)&h1, g_h1);
    cudaGetSymbolAddress((void**)&h2, g_h2);
    cudaGetSymbolAddress((void**)&gpre, g_gpre);
    cudaGetSymbolAddress((void**)&apl, g_apply);
    cudaGetSymbolAddress((void**)&wtf, g_wtf);
    float* Wih0c = wtf;
    float* Wih1c = wtf + 1048576;
    float* gW1c = wtf + 3145728;
    float* gW2c = wtf + 4194304;

    cudaFuncSetAttribute(tf32_gemm_kernel<0>, cudaFuncAttributeMaxDynamicSharedMemorySize, GEMM_SMEM);
    cudaFuncSetAttribute(tf32_gemm_kernel<1>, cudaFuncAttributeMaxDynamicSharedMemorySize, GEMM_SMEM);

    // 0. tf32-round weights into scratch
    cvtw_kernel<<<4096, 256>>>(Wih0, Wih0c, 1048576);
    cvtw_kernel<<<8192, 256>>>(Wih1, Wih1c, 2097152);
    cvtw_kernel<<<4096, 256>>>(gW1, gW1c, 1048576);
    cvtw_kernel<<<4096, 256>>>(gW2, gW2c, 1048576);
    // 1. LayerNorm(features) -> xn (tf32-rounded)
    ln_kernel<512, false><<<NROWS, 128>>>(features, xn, ln_g, ln_b);
    // 2. decide scan -> apply
    decide_kernel<<<1, 32>>>(rnd, mask, apl);
    // 3. layer0 input projections: zx = xn @ Wih0cat^T + b0   [32768 x 2048]
    tf32_gemm_kernel<0><<<dim3(16, 256), 256, GEMM_SMEM>>>(xn, xn, 512, 512, Wih0c, b0, zx, 2048, nullptr, nullptr);
    // 4. layer0 recurrence -> h1  (8 clusters x 8 CTAs, dual-chain)
    lstm_kernel<<<64, 256>>>(zx, Whh0, h1);
    // 5. layer1 input projections: zx = h1 @ Wih1cat^T + b1
    tf32_gemm_kernel<0><<<dim3(16, 256), 256, GEMM_SMEM>>>(h1, h1, 512, 512, Wih1c, b1, zx, 2048, nullptr, nullptr);
    // 6. layer1 recurrence -> h2
    lstm_kernel<<<64, 256>>>(zx, Whh1, h2);
    // 7. gpre = [xn | h2] @ gW1^T + gb1   [32768 x 1024]
    tf32_gemm_kernel<0><<<dim3(8, 256), 256, GEMM_SMEM>>>(xn, h2, 512, 1024, gW1c, gb1, gpre, 1024, nullptr, nullptr);
    // 8. LN + ReLU in place (tf32-rounded)
    ln_kernel<1024, true><<<NROWS, 128>>>(gpre, gpre, gln_g, gln_b);
    // 9. orn (first 512 cols of gW2) + ornament transform + apply-select -> out
    tf32_gemm_kernel<1><<<dim3(4, 256), 256, GEMM_SMEM>>>(gpre, gpre, 1024, 1024, gW2c, gb2, out, 512, apl, xn);
}